// round 14
// baseline (speedup 1.0000x reference)
#include <cuda_runtime.h>
#include <cuda_fp16.h>
#include <math.h>

#define T_  2048
#define C_  1024
#define H_  16
#define D_  64
#define L_  4
#define V_  32000
#define C3_ 3072
#define C4_ 4096

// ---- scratch (no allocation allowed) ----
__device__ float  g_x[T_ * C_];          // fp32 residual stream
__device__ __half gh_h[T_ * C_];         // LN output (A operand)
__device__ __half gh_qkv[T_ * C3_];
__device__ __half gh_y[T_ * C_];
__device__ __half gh_g[T_ * C4_];
// fp16 weights (converted per launch)
__device__ __half gh_attnw[L_ * C3_ * C_];
__device__ __half gh_projw[L_ * C_ * C_];
__device__ __half gh_fcw[L_ * C4_ * C_];
__device__ __half gh_fcpw[L_ * C_ * C4_];
__device__ __half gh_wte[V_ * C_];

// ---------------- f32 -> f16 conversion ----------------
__global__ void f2h_k(const float* __restrict__ s, __half* __restrict__ d, int n) {
    int stride = gridDim.x * blockDim.x * 4;
    for (int i = (blockIdx.x * blockDim.x + threadIdx.x) * 4; i < n; i += stride) {
        float4 v = *(const float4*)(s + i);
        __half2 h0 = __floats2half2_rn(v.x, v.y);
        __half2 h1 = __floats2half2_rn(v.z, v.w);
        uint2 u; u.x = *(unsigned*)&h0; u.y = *(unsigned*)&h1;
        *(uint2*)(d + i) = u;
    }
}

// ---------------- embedding ----------------
__global__ void embed_k(const int* __restrict__ ids, const float* __restrict__ wte,
                        const float* __restrict__ wpe, float* __restrict__ x) {
    int t = blockIdx.x;
    int id = ids[t];
    const float* wt = wte + (size_t)id * C_;
    const float* wp = wpe + (size_t)t * C_;
    float* xr = x + (size_t)t * C_;
    for (int c = threadIdx.x; c < C_; c += blockDim.x)
        xr[c] = wt[c] + wp[c];
}

// ---------------- layernorm (fp32 in, fp16 out) ----------------
__global__ __launch_bounds__(256) void ln_k(const float* __restrict__ x,
                                            const float* __restrict__ w,
                                            const float* __restrict__ b,
                                            __half* __restrict__ out) {
    int row = blockIdx.x;
    int tid = threadIdx.x;
    const float* xr = x + (size_t)row * C_;
    float4 v = *(const float4*)(xr + tid * 4);
    float s = v.x + v.y + v.z + v.w;
    float ss = v.x * v.x + v.y * v.y + v.z * v.z + v.w * v.w;
#pragma unroll
    for (int o = 16; o > 0; o >>= 1) {
        s  += __shfl_xor_sync(0xffffffffu, s, o);
        ss += __shfl_xor_sync(0xffffffffu, ss, o);
    }
    __shared__ float rs[8], rss[8];
    __shared__ float stats[2];
    int wid = tid >> 5;
    if ((tid & 31) == 0) { rs[wid] = s; rss[wid] = ss; }
    __syncthreads();
    if (tid == 0) {
        float ts = 0.f, tss = 0.f;
#pragma unroll
        for (int i = 0; i < 8; i++) { ts += rs[i]; tss += rss[i]; }
        float mean = ts * (1.0f / C_);
        float var = tss * (1.0f / C_) - mean * mean;
        stats[0] = mean;
        stats[1] = rsqrtf(var + 1e-5f);
    }
    __syncthreads();
    float mean = stats[0], rstd = stats[1];
    const float4 w4 = *(const float4*)(w + tid * 4);
    const float4 b4 = *(const float4*)(b + tid * 4);
    __half2 h0 = __floats2half2_rn((v.x - mean) * rstd * w4.x + b4.x,
                                   (v.y - mean) * rstd * w4.y + b4.y);
    __half2 h1 = __floats2half2_rn((v.z - mean) * rstd * w4.z + b4.z,
                                   (v.w - mean) * rstd * w4.w + b4.w);
    uint2 u; u.x = *(unsigned*)&h0; u.y = *(unsigned*)&h1;
    *(uint2*)(out + (size_t)row * C_ + tid * 4) = u;
}

// ---------------- common helpers ----------------
__device__ __forceinline__ float gelu_f(float x) {
    return 0.5f * x * (1.0f + erff(x * 0.70710678118654752f));
}

__device__ __forceinline__ void mma_f16(float* c, const unsigned* a, const unsigned* b) {
    asm volatile(
        "mma.sync.aligned.m16n8k16.row.col.f32.f16.f16.f32 "
        "{%0,%1,%2,%3}, {%4,%5,%6,%7}, {%8,%9}, {%0,%1,%2,%3};"
        : "+f"(c[0]), "+f"(c[1]), "+f"(c[2]), "+f"(c[3])
        : "r"(a[0]), "r"(a[1]), "r"(a[2]), "r"(a[3]), "r"(b[0]), "r"(b[1]));
}

__device__ __forceinline__ void ldsm_x2_t(unsigned& r0, unsigned& r1, unsigned addr) {
    asm volatile("ldmatrix.sync.aligned.m8n8.x2.trans.shared.b16 {%0,%1}, [%2];"
                 : "=r"(r0), "=r"(r1) : "r"(addr));
}

__device__ __forceinline__ void cp16(unsigned s, const void* g) {
    asm volatile("cp.async.cg.shared.global [%0], [%1], 16;" :: "r"(s), "l"(g));
}
#define CP_COMMIT() asm volatile("cp.async.commit_group;" ::: "memory")
#define CP_WAIT0()  asm volatile("cp.async.wait_group 0;" ::: "memory")

// ---------------- FP16 NT GEMM, cp.async double-buffered ----------------
// C[m,n] = sum_k A[m,k]*B[n,k]. Tile 128 x BN_T x 32, 256 thr (8 warps 2x4).
// Warp tile 64 x (BN_T/4). One __syncthreads per k-iter; copies overlap mma.
#define BM 128
#define BK 32
#define HP 40  // smem pitch in halves (80 B, 16B-aligned rows)

// MODE bit0: +bias[n]; bit1: += C (residual, float only); bit2: gelu
template <int MODE, int BN_T, typename OutT>
__global__ __launch_bounds__(256) void gemm_h(const __half* __restrict__ A,
                                              const __half* __restrict__ B,
                                              const float* __restrict__ bias,
                                              OutT* __restrict__ Cmat,
                                              int M, int N, int K) {
    constexpr int NT = BN_T / 32;          // n-tiles (8 cols each) per warp: 4 or 8
    extern __shared__ __half dsm[];
    __half* As = dsm;                       // [2][BM*HP]
    __half* Bs = dsm + 2 * BM * HP;         // [2][BN_T*HP]

    int tid = threadIdx.x;
    int bm0 = blockIdx.y * BM, bn0 = blockIdx.x * BN_T;
    int wid = tid >> 5, lane = tid & 31;
    int g = lane >> 2, tg = lane & 3;
    int wm = (wid >> 2) * 64;
    int wn = (wid & 3) * (NT * 8);

    const unsigned saB = (unsigned)__cvta_generic_to_shared(As);
    const unsigned sbB = (unsigned)__cvta_generic_to_shared(Bs);
    int lr = tid >> 1;
    int seg = (tid & 1) * 16;

    auto issue = [&](int s, int k0) {
        unsigned sa = saB + ((s * BM + lr) * HP + seg) * 2;
        const __half* ga = A + (size_t)(bm0 + lr) * K + k0 + seg;
        cp16(sa, ga);
        cp16(sa + 16, ga + 8);
        if (BN_T == 256) {
            unsigned sb = sbB + ((s * BN_T + tid) * HP) * 2;
            const __half* gb = B + (size_t)(bn0 + tid) * K + k0;
            cp16(sb, gb); cp16(sb + 16, gb + 8);
            cp16(sb + 32, gb + 16); cp16(sb + 48, gb + 24);
        } else {
            unsigned sb = sbB + ((s * BN_T + lr) * HP + seg) * 2;
            const __half* gb = B + (size_t)(bn0 + lr) * K + k0 + seg;
            cp16(sb, gb); cp16(sb + 16, gb + 8);
        }
        CP_COMMIT();
    };

    float acc[4][NT][4];
#pragma unroll
    for (int i = 0; i < 4; i++)
#pragma unroll
        for (int j = 0; j < NT; j++)
#pragma unroll
            for (int r = 0; r < 4; r++) acc[i][j][r] = 0.f;

    issue(0, 0);

    int niter = K / BK;
    for (int it = 0; it < niter; it++) {
        int st = it & 1;
        CP_WAIT0();
        __syncthreads();
        if (it + 1 < niter) issue(st ^ 1, (it + 1) * BK);

        const __half* Ast = As + st * BM * HP;
        const __half* Bst = Bs + st * BN_T * HP;
#pragma unroll
        for (int ks = 0; ks < 2; ks++) {
            int k = ks * 16;
            unsigned af[4][4], bf[NT][2];
#pragma unroll
            for (int mt = 0; mt < 4; mt++) {
                int mb = wm + mt * 16;
                af[mt][0] = *(const unsigned*)&Ast[(mb + g) * HP + k + tg * 2];
                af[mt][1] = *(const unsigned*)&Ast[(mb + g + 8) * HP + k + tg * 2];
                af[mt][2] = *(const unsigned*)&Ast[(mb + g) * HP + k + tg * 2 + 8];
                af[mt][3] = *(const unsigned*)&Ast[(mb + g + 8) * HP + k + tg * 2 + 8];
            }
#pragma unroll
            for (int nt = 0; nt < NT; nt++) {
                int nb = wn + nt * 8;
                bf[nt][0] = *(const unsigned*)&Bst[(nb + g) * HP + k + tg * 2];
                bf[nt][1] = *(const unsigned*)&Bst[(nb + g) * HP + k + tg * 2 + 8];
            }
#pragma unroll
            for (int mt = 0; mt < 4; mt++)
#pragma unroll
                for (int nt = 0; nt < NT; nt++)
                    mma_f16(acc[mt][nt], af[mt], bf[nt]);
        }
    }

    // epilogue
#pragma unroll
    for (int mt = 0; mt < 4; mt++) {
#pragma unroll
        for (int nt = 0; nt < NT; nt++) {
            int n = bn0 + wn + nt * 8 + 2 * tg;
            float bsum0 = 0.f, bsum1 = 0.f;
            if (MODE & 1) { bsum0 = bias[n]; bsum1 = bias[n + 1]; }
#pragma unroll
            for (int h = 0; h < 2; h++) {
                int m = bm0 + wm + mt * 16 + g + h * 8;
                float v0 = acc[mt][nt][2 * h] + bsum0;
                float v1 = acc[mt][nt][2 * h + 1] + bsum1;
                if (MODE & 4) { v0 = gelu_f(v0); v1 = gelu_f(v1); }
                size_t off = (size_t)m * N + n;
                if (MODE & 2) {
                    float2 old = *(const float2*)((const float*)Cmat + off);
                    v0 += old.x; v1 += old.y;
                }
                if (sizeof(OutT) == 2) {
                    __half2 hv = __floats2half2_rn(v0, v1);
                    *(__half2*)((__half*)Cmat + off) = hv;
                } else {
                    float2 st2; st2.x = v0; st2.y = v1;
                    *(float2*)((float*)Cmat + off) = st2;
                }
            }
        }
    }
}

// ---------------- FP16 tensor-core causal flash attention ----------------
// Block 128 thr (4 warps), tile 64 queries x one head. P kept in registers.
// blockIdx.x reversed so the longest (largest-qt) CTAs launch first.
#define KP2 72  // halves pitch (144 B/row)

__global__ __launch_bounds__(128) void attn_k(const __half* __restrict__ qkv,
                                              __half* __restrict__ y) {
    int qt = gridDim.x - 1 - blockIdx.x;   // longest blocks first
    int head = blockIdx.y;
    int tid = threadIdx.x;
    int w = tid >> 5, lane = tid & 31;
    int g = lane >> 2, tg = lane & 3;

    __shared__ __half Ks[64 * KP2];
    __shared__ __half Vs[64 * KP2];

    // Q fragments (pre-scaled by 1/8, exact in fp16)
    unsigned qa[4][4];
    {
        const __half2 sc = __float2half2_rn(0.125f);
        int r0 = qt * 64 + w * 16 + g;
        const __half* q0 = qkv + (size_t)r0 * C3_ + head * 64;
        const __half* q1 = q0 + (size_t)8 * C3_;
#pragma unroll
        for (int kc = 0; kc < 4; kc++) {
            __half2 a0 = __hmul2(*(const __half2*)(q0 + kc * 16 + tg * 2), sc);
            __half2 a1 = __hmul2(*(const __half2*)(q1 + kc * 16 + tg * 2), sc);
            __half2 a2 = __hmul2(*(const __half2*)(q0 + kc * 16 + tg * 2 + 8), sc);
            __half2 a3 = __hmul2(*(const __half2*)(q1 + kc * 16 + tg * 2 + 8), sc);
            qa[kc][0] = *(unsigned*)&a0; qa[kc][1] = *(unsigned*)&a1;
            qa[kc][2] = *(unsigned*)&a2; qa[kc][3] = *(unsigned*)&a3;
        }
    }

    float o[8][4];
#pragma unroll
    for (int nf = 0; nf < 8; nf++)
#pragma unroll
        for (int r = 0; r < 4; r++) o[nf][r] = 0.f;
    float m0 = -1e30f, m1 = -1e30f, l0 = 0.f, l1 = 0.f;

    int lrow = tid >> 1;
    int sec = (tid & 1) * 32;

    for (int kt = 0; kt <= qt; ++kt) {
        __syncthreads();  // readers of previous tile done
        {
            const __half* kp = qkv + (size_t)(kt * 64 + lrow) * C3_ + C_ + head * 64 + sec;
            const __half* vp = kp + C_;
#pragma unroll
            for (int i = 0; i < 4; i++) {
                *(uint4*)&Ks[lrow * KP2 + sec + i * 8] = *(const uint4*)(kp + i * 8);
                *(uint4*)&Vs[lrow * KP2 + sec + i * 8] = *(const uint4*)(vp + i * 8);
            }
        }
        __syncthreads();

        // S = Q @ K^T  (warp: 16 x 64)
        float s[8][4];
#pragma unroll
        for (int nf = 0; nf < 8; nf++)
#pragma unroll
            for (int r = 0; r < 4; r++) s[nf][r] = 0.f;
#pragma unroll
        for (int kc = 0; kc < 4; kc++) {
#pragma unroll
            for (int nf = 0; nf < 8; nf++) {
                unsigned bf[2];
                bf[0] = *(const unsigned*)&Ks[(nf * 8 + g) * KP2 + kc * 16 + tg * 2];
                bf[1] = *(const unsigned*)&Ks[(nf * 8 + g) * KP2 + kc * 16 + tg * 2 + 8];
                mma_f16(s[nf], qa[kc], bf);
            }
        }

        // causal mask on diagonal tile
        if (kt == qt) {
            int r0 = w * 16 + g, r1 = r0 + 8;
#pragma unroll
            for (int nf = 0; nf < 8; nf++) {
                int c0 = nf * 8 + 2 * tg, c1 = c0 + 1;
                if (c0 > r0) s[nf][0] = -1e30f;
                if (c1 > r0) s[nf][1] = -1e30f;
                if (c0 > r1) s[nf][2] = -1e30f;
                if (c1 > r1) s[nf][3] = -1e30f;
            }
        }

        // online softmax
        float mx0 = -1e30f, mx1 = -1e30f;
#pragma unroll
        for (int nf = 0; nf < 8; nf++) {
            mx0 = fmaxf(mx0, fmaxf(s[nf][0], s[nf][1]));
            mx1 = fmaxf(mx1, fmaxf(s[nf][2], s[nf][3]));
        }
        mx0 = fmaxf(mx0, __shfl_xor_sync(0xffffffffu, mx0, 1));
        mx0 = fmaxf(mx0, __shfl_xor_sync(0xffffffffu, mx0, 2));
        mx1 = fmaxf(mx1, __shfl_xor_sync(0xffffffffu, mx1, 1));
        mx1 = fmaxf(mx1, __shfl_xor_sync(0xffffffffu, mx1, 2));

        float nm0 = fmaxf(m0, mx0), nm1 = fmaxf(m1, mx1);
        float f0 = __expf(m0 - nm0), f1 = __expf(m1 - nm1);
        m0 = nm0; m1 = nm1;

        float sum0 = 0.f, sum1 = 0.f;
#pragma unroll
        for (int nf = 0; nf < 8; nf++) {
            s[nf][0] = __expf(s[nf][0] - m0);
            s[nf][1] = __expf(s[nf][1] - m0);
            s[nf][2] = __expf(s[nf][2] - m1);
            s[nf][3] = __expf(s[nf][3] - m1);
            sum0 += s[nf][0] + s[nf][1];
            sum1 += s[nf][2] + s[nf][3];
        }
        sum0 += __shfl_xor_sync(0xffffffffu, sum0, 1);
        sum0 += __shfl_xor_sync(0xffffffffu, sum0, 2);
        sum1 += __shfl_xor_sync(0xffffffffu, sum1, 1);
        sum1 += __shfl_xor_sync(0xffffffffu, sum1, 2);
        l0 = l0 * f0 + sum0;
        l1 = l1 * f1 + sum1;

#pragma unroll
        for (int nf = 0; nf < 8; nf++) {
            o[nf][0] *= f0; o[nf][1] *= f0;
            o[nf][2] *= f1; o[nf][3] *= f1;
        }

        // O += P @ V : P fragments directly from the s registers
#pragma unroll
        for (int kc = 0; kc < 4; kc++) {
            unsigned pa[4];
            __half2 p0 = __floats2half2_rn(s[2 * kc][0], s[2 * kc][1]);
            __half2 p1 = __floats2half2_rn(s[2 * kc][2], s[2 * kc][3]);
            __half2 p2 = __floats2half2_rn(s[2 * kc + 1][0], s[2 * kc + 1][1]);
            __half2 p3 = __floats2half2_rn(s[2 * kc + 1][2], s[2 * kc + 1][3]);
            pa[0] = *(unsigned*)&p0; pa[1] = *(unsigned*)&p1;
            pa[2] = *(unsigned*)&p2; pa[3] = *(unsigned*)&p3;
#pragma unroll
            for (int nf = 0; nf < 8; nf++) {
                unsigned b0, b1;
                unsigned addr = (unsigned)__cvta_generic_to_shared(
                    &Vs[(kc * 16 + (lane & 15)) * KP2 + nf * 8]);
                ldsm_x2_t(b0, b1, addr);
                unsigned bv[2] = {b0, b1};
                mma_f16(o[nf], pa, bv);
            }
        }
    }

    // epilogue: normalize + write fp16
    float inv0 = 1.0f / l0, inv1 = 1.0f / l1;
    int r0 = qt * 64 + w * 16 + g;
    __half* y0 = y + (size_t)r0 * C_ + head * 64;
    __half* y1 = y0 + (size_t)8 * C_;
#pragma unroll
    for (int nf = 0; nf < 8; nf++) {
        int c = nf * 8 + 2 * tg;
        *(__half2*)(y0 + c) = __floats2half2_rn(o[nf][0] * inv0, o[nf][1] * inv0);
        *(__half2*)(y1 + c) = __floats2half2_rn(o[nf][2] * inv1, o[nf][3] * inv1);
    }
}

// ---------------- launch ----------------
#define SMEM_W (2 * (BM + 256) * HP * 2)  // 61440 B (BN=256)
#define SMEM_N (2 * (BM + 128) * HP * 2)  // 40960 B (BN=128)

extern "C" void kernel_launch(void* const* d_in, const int* in_sizes, int n_in,
                              void* d_out, int out_size) {
    const int*   ids   = (const int*)d_in[0];
    const float* wte   = (const float*)d_in[1];
    const float* wpe   = (const float*)d_in[2];
    const float* ln1w  = (const float*)d_in[3];
    const float* ln1b  = (const float*)d_in[4];
    const float* attnw = (const float*)d_in[5];
    const float* attnb = (const float*)d_in[6];
    const float* projw = (const float*)d_in[7];
    const float* projb = (const float*)d_in[8];
    const float* ln2w  = (const float*)d_in[9];
    const float* ln2b  = (const float*)d_in[10];
    const float* fcw   = (const float*)d_in[11];
    const float* fcb   = (const float*)d_in[12];
    const float* fcpw  = (const float*)d_in[13];
    const float* fcpb  = (const float*)d_in[14];
    const float* lnfw  = (const float*)d_in[15];
    const float* lnfb  = (const float*)d_in[16];
    float* out = (float*)d_out;

    cudaFuncSetAttribute(gemm_h<1, 256, __half>,
                         cudaFuncAttributeMaxDynamicSharedMemorySize, SMEM_W);
    cudaFuncSetAttribute(gemm_h<5, 256, __half>,
                         cudaFuncAttributeMaxDynamicSharedMemorySize, SMEM_W);
    cudaFuncSetAttribute(gemm_h<0, 256, float>,
                         cudaFuncAttributeMaxDynamicSharedMemorySize, SMEM_W);
    cudaFuncSetAttribute(gemm_h<3, 128, float>,
                         cudaFuncAttributeMaxDynamicSharedMemorySize, SMEM_N);

    float* xp;
    __half *hp, *qkvp, *yp, *gp;
    __half *wA, *wP, *wF, *wFP, *wT;
    cudaGetSymbolAddress((void**)&xp, g_x);
    cudaGetSymbolAddress((void**)&hp, gh_h);
    cudaGetSymbolAddress((void**)&qkvp, gh_qkv);
    cudaGetSymbolAddress((void**)&yp, gh_y);
    cudaGetSymbolAddress((void**)&gp, gh_g);
    cudaGetSymbolAddress((void**)&wA, gh_attnw);
    cudaGetSymbolAddress((void**)&wP, gh_projw);
    cudaGetSymbolAddress((void**)&wF, gh_fcw);
    cudaGetSymbolAddress((void**)&wFP, gh_fcpw);
    cudaGetSymbolAddress((void**)&wT, gh_wte);

    // weight conversions (graph-capturable, deterministic)
    f2h_k<<<2048, 256>>>(attnw, wA, L_ * C3_ * C_);
    f2h_k<<<2048, 256>>>(projw, wP, L_ * C_ * C_);
    f2h_k<<<2048, 256>>>(fcw, wF, L_ * C4_ * C_);
    f2h_k<<<2048, 256>>>(fcpw, wFP, L_ * C_ * C4_);
    f2h_k<<<4096, 256>>>(wte, wT, V_ * C_);

    embed_k<<<T_, 256>>>(ids, wte, wpe, xp);

    for (int l = 0; l < L_; l++) {
        ln_k<<<T_, 256>>>(xp, ln1w + l * C_, ln1b + l * C_, hp);
        gemm_h<1, 256, __half><<<dim3(C3_ / 256, T_ / BM), 256, SMEM_W>>>(
            hp, wA + (size_t)l * C3_ * C_, attnb + l * C3_, qkvp, T_, C3_, C_);
        attn_k<<<dim3(T_ / 64, H_), 128>>>(qkvp, yp);
        gemm_h<3, 128, float><<<dim3(C_ / 128, T_ / BM), 256, SMEM_N>>>(
            yp, wP + (size_t)l * C_ * C_, projb + l * C_, xp, T_, C_, C_);
        ln_k<<<T_, 256>>>(xp, ln2w + l * C_, ln2b + l * C_, hp);
        gemm_h<5, 256, __half><<<dim3(C4_ / 256, T_ / BM), 256, SMEM_W>>>(
            hp, wF + (size_t)l * C4_ * C_, fcb + l * C4_, gp, T_, C4_, C_);
        gemm_h<3, 128, float><<<dim3(C_ / 128, T_ / BM), 256, SMEM_N>>>(
            gp, wFP + (size_t)l * C_ * C4_, fcpb + l * C_, xp, T_, C_, C4_);
    }

    ln_k<<<T_, 256>>>(xp, lnfw, lnfb, hp);
    gemm_h<0, 256, float><<<dim3(V_ / 256, T_ / BM), 256, SMEM_W>>>(
        hp, wT, nullptr, out, T_, V_, C_);
}

// round 16
// speedup vs baseline: 1.0211x; 1.0211x over previous
#include <cuda_runtime.h>
#include <cuda_fp16.h>
#include <math.h>

#define T_  2048
#define C_  1024
#define H_  16
#define D_  64
#define L_  4
#define V_  32000
#define C3_ 3072
#define C4_ 4096

// ---- scratch (no allocation allowed) ----
__device__ float  g_x[T_ * C_];          // fp32 residual stream
__device__ __half gh_h[T_ * C_];         // LN output (A operand)
__device__ __half gh_qkv[T_ * C3_];
__device__ __half gh_y[T_ * C_];
__device__ __half gh_g[T_ * C4_];
// fp16 weights (converted per launch)
__device__ __half gh_attnw[L_ * C3_ * C_];
__device__ __half gh_projw[L_ * C_ * C_];
__device__ __half gh_fcw[L_ * C4_ * C_];
__device__ __half gh_fcpw[L_ * C_ * C4_];
__device__ __half gh_wte[V_ * C_];

// ---------------- f32 -> f16 conversion ----------------
__global__ void f2h_k(const float* __restrict__ s, __half* __restrict__ d, int n) {
    int stride = gridDim.x * blockDim.x * 4;
    for (int i = (blockIdx.x * blockDim.x + threadIdx.x) * 4; i < n; i += stride) {
        float4 v = *(const float4*)(s + i);
        __half2 h0 = __floats2half2_rn(v.x, v.y);
        __half2 h1 = __floats2half2_rn(v.z, v.w);
        uint2 u; u.x = *(unsigned*)&h0; u.y = *(unsigned*)&h1;
        *(uint2*)(d + i) = u;
    }
}

// ---------------- embedding ----------------
__global__ void embed_k(const int* __restrict__ ids, const float* __restrict__ wte,
                        const float* __restrict__ wpe, float* __restrict__ x) {
    int t = blockIdx.x;
    int id = ids[t];
    const float* wt = wte + (size_t)id * C_;
    const float* wp = wpe + (size_t)t * C_;
    float* xr = x + (size_t)t * C_;
    for (int c = threadIdx.x; c < C_; c += blockDim.x)
        xr[c] = wt[c] + wp[c];
}

// ---------------- layernorm (fp32 in, fp16 out) ----------------
__global__ __launch_bounds__(256) void ln_k(const float* __restrict__ x,
                                            const float* __restrict__ w,
                                            const float* __restrict__ b,
                                            __half* __restrict__ out) {
    int row = blockIdx.x;
    int tid = threadIdx.x;
    const float* xr = x + (size_t)row * C_;
    float4 v = *(const float4*)(xr + tid * 4);
    float s = v.x + v.y + v.z + v.w;
    float ss = v.x * v.x + v.y * v.y + v.z * v.z + v.w * v.w;
#pragma unroll
    for (int o = 16; o > 0; o >>= 1) {
        s  += __shfl_xor_sync(0xffffffffu, s, o);
        ss += __shfl_xor_sync(0xffffffffu, ss, o);
    }
    __shared__ float rs[8], rss[8];
    __shared__ float stats[2];
    int wid = tid >> 5;
    if ((tid & 31) == 0) { rs[wid] = s; rss[wid] = ss; }
    __syncthreads();
    if (tid == 0) {
        float ts = 0.f, tss = 0.f;
#pragma unroll
        for (int i = 0; i < 8; i++) { ts += rs[i]; tss += rss[i]; }
        float mean = ts * (1.0f / C_);
        float var = tss * (1.0f / C_) - mean * mean;
        stats[0] = mean;
        stats[1] = rsqrtf(var + 1e-5f);
    }
    __syncthreads();
    float mean = stats[0], rstd = stats[1];
    const float4 w4 = *(const float4*)(w + tid * 4);
    const float4 b4 = *(const float4*)(b + tid * 4);
    __half2 h0 = __floats2half2_rn((v.x - mean) * rstd * w4.x + b4.x,
                                   (v.y - mean) * rstd * w4.y + b4.y);
    __half2 h1 = __floats2half2_rn((v.z - mean) * rstd * w4.z + b4.z,
                                   (v.w - mean) * rstd * w4.w + b4.w);
    uint2 u; u.x = *(unsigned*)&h0; u.y = *(unsigned*)&h1;
    *(uint2*)(out + (size_t)row * C_ + tid * 4) = u;
}

// ---------------- common helpers ----------------
__device__ __forceinline__ float gelu_f(float x) {
    return 0.5f * x * (1.0f + erff(x * 0.70710678118654752f));
}

__device__ __forceinline__ void mma_f16(float* c, const unsigned* a, const unsigned* b) {
    asm volatile(
        "mma.sync.aligned.m16n8k16.row.col.f32.f16.f16.f32 "
        "{%0,%1,%2,%3}, {%4,%5,%6,%7}, {%8,%9}, {%0,%1,%2,%3};"
        : "+f"(c[0]), "+f"(c[1]), "+f"(c[2]), "+f"(c[3])
        : "r"(a[0]), "r"(a[1]), "r"(a[2]), "r"(a[3]), "r"(b[0]), "r"(b[1]));
}

__device__ __forceinline__ void ldsm_x2_t(unsigned& r0, unsigned& r1, unsigned addr) {
    asm volatile("ldmatrix.sync.aligned.m8n8.x2.trans.shared.b16 {%0,%1}, [%2];"
                 : "=r"(r0), "=r"(r1) : "r"(addr));
}

// ---------------- FP16 NT GEMM, double-buffered SMEM (round-11 config) ----------------
// C[m,n] = sum_k A[m,k]*B[n,k], A/B fp16 in gmem. Tile 128x128x32, 8 warps.
#define BM 128
#define BN 128
#define BK 32
#define HP 40  // smem pitch in halves

// MODE bit0: +bias[n]; bit1: += C (residual, float only); bit2: gelu
template <int MODE, typename OutT>
__global__ __launch_bounds__(256) void gemm_h(const __half* __restrict__ A,
                                              const __half* __restrict__ B,
                                              const float* __restrict__ bias,
                                              OutT* __restrict__ Cmat,
                                              int M, int N, int K) {
    __shared__ __half As[2][BM * HP];
    __shared__ __half Bs[2][BN * HP];

    int tid = threadIdx.x;
    int bm0 = blockIdx.y * BM, bn0 = blockIdx.x * BN;
    int wid = tid >> 5, lane = tid & 31;
    int g = lane >> 2, tg = lane & 3;
    int wm = (wid >> 2) * 64;
    int wn = (wid & 3) * 32;

    int lr = tid >> 1;              // 0..127 (row)
    int seg = (tid & 1) * 16;       // 0 / 16 halves

    const __half* Ap = A + (size_t)(bm0 + lr) * K + seg;
    const __half* Bp = B + (size_t)(bn0 + lr) * K + seg;

    float acc[4][4][4];
#pragma unroll
    for (int i = 0; i < 4; i++)
#pragma unroll
        for (int j = 0; j < 4; j++)
#pragma unroll
            for (int r = 0; r < 4; r++) acc[i][j][r] = 0.f;

    // full-coverage staging: 2 x uint4 (16 halves) per thread per operand
    uint4 la0 = *(const uint4*)Ap;
    uint4 la1 = *(const uint4*)(Ap + 8);
    uint4 lb0 = *(const uint4*)Bp;
    uint4 lb1 = *(const uint4*)(Bp + 8);
    *(uint4*)&As[0][lr * HP + seg]     = la0;
    *(uint4*)&As[0][lr * HP + seg + 8] = la1;
    *(uint4*)&Bs[0][lr * HP + seg]     = lb0;
    *(uint4*)&Bs[0][lr * HP + seg + 8] = lb1;
    __syncthreads();

    int niter = K / BK;
    for (int it = 0; it < niter; it++) {
        int st = it & 1;
        if (it + 1 < niter) {
            const __half* An = Ap + (it + 1) * BK;
            const __half* Bn = Bp + (it + 1) * BK;
            la0 = *(const uint4*)An;
            la1 = *(const uint4*)(An + 8);
            lb0 = *(const uint4*)Bn;
            lb1 = *(const uint4*)(Bn + 8);
        }
        const __half* Ast = As[st];
        const __half* Bst = Bs[st];
#pragma unroll
        for (int ks = 0; ks < 2; ks++) {
            int k = ks * 16;
            unsigned af[4][4], bf[4][2];
#pragma unroll
            for (int mt = 0; mt < 4; mt++) {
                int mb = wm + mt * 16;
                af[mt][0] = *(const unsigned*)&Ast[(mb + g) * HP + k + tg * 2];
                af[mt][1] = *(const unsigned*)&Ast[(mb + g + 8) * HP + k + tg * 2];
                af[mt][2] = *(const unsigned*)&Ast[(mb + g) * HP + k + tg * 2 + 8];
                af[mt][3] = *(const unsigned*)&Ast[(mb + g + 8) * HP + k + tg * 2 + 8];
            }
#pragma unroll
            for (int nt = 0; nt < 4; nt++) {
                int nb = wn + nt * 8;
                bf[nt][0] = *(const unsigned*)&Bst[(nb + g) * HP + k + tg * 2];
                bf[nt][1] = *(const unsigned*)&Bst[(nb + g) * HP + k + tg * 2 + 8];
            }
#pragma unroll
            for (int mt = 0; mt < 4; mt++)
#pragma unroll
                for (int nt = 0; nt < 4; nt++)
                    mma_f16(acc[mt][nt], af[mt], bf[nt]);
        }
        if (it + 1 < niter) {
            *(uint4*)&As[st ^ 1][lr * HP + seg]     = la0;
            *(uint4*)&As[st ^ 1][lr * HP + seg + 8] = la1;
            *(uint4*)&Bs[st ^ 1][lr * HP + seg]     = lb0;
            *(uint4*)&Bs[st ^ 1][lr * HP + seg + 8] = lb1;
        }
        __syncthreads();
    }

    // epilogue
#pragma unroll
    for (int mt = 0; mt < 4; mt++) {
#pragma unroll
        for (int nt = 0; nt < 4; nt++) {
            int n = bn0 + wn + nt * 8 + 2 * tg;
            float bsum0 = 0.f, bsum1 = 0.f;
            if (MODE & 1) { bsum0 = bias[n]; bsum1 = bias[n + 1]; }
#pragma unroll
            for (int h = 0; h < 2; h++) {
                int m = bm0 + wm + mt * 16 + g + h * 8;
                float v0 = acc[mt][nt][2 * h] + bsum0;
                float v1 = acc[mt][nt][2 * h + 1] + bsum1;
                if (MODE & 4) { v0 = gelu_f(v0); v1 = gelu_f(v1); }
                size_t off = (size_t)m * N + n;
                if (MODE & 2) {
                    float2 old = *(const float2*)((const float*)Cmat + off);
                    v0 += old.x; v1 += old.y;
                }
                if (sizeof(OutT) == 2) {
                    __half2 hv = __floats2half2_rn(v0, v1);
                    *(__half2*)((__half*)Cmat + off) = hv;
                } else {
                    float2 st2; st2.x = v0; st2.y = v1;
                    *(float2*)((float*)Cmat + off) = st2;
                }
            }
        }
    }
}

// ---------------- FP16 tensor-core causal flash attention ----------------
// Block 256 thr (8 warps), tile 128 queries x one head; warp w owns 16 rows.
// K/V 64-key tiles staged once per 128 queries (half the fill traffic of the
// 64-query version). Longest blocks launch first (reversed blockIdx.x).
#define KP2 72  // halves pitch (144 B/row)

__global__ __launch_bounds__(256) void attn_k(const __half* __restrict__ qkv,
                                              __half* __restrict__ y) {
    int qt = gridDim.x - 1 - blockIdx.x;   // 0..T/128-1, longest first
    int head = blockIdx.y;
    int tid = threadIdx.x;
    int w = tid >> 5, lane = tid & 31;
    int g = lane >> 2, tg = lane & 3;
    int q0 = qt * 128;

    __shared__ __half Ks[64 * KP2];
    __shared__ __half Vs[64 * KP2];

    // Q fragments (pre-scaled by 1/8, exact in fp16)
    unsigned qa[4][4];
    {
        const __half2 sc = __float2half2_rn(0.125f);
        int r0 = q0 + w * 16 + g;
        const __half* qp0 = qkv + (size_t)r0 * C3_ + head * 64;
        const __half* qp1 = qp0 + (size_t)8 * C3_;
#pragma unroll
        for (int kc = 0; kc < 4; kc++) {
            __half2 a0 = __hmul2(*(const __half2*)(qp0 + kc * 16 + tg * 2), sc);
            __half2 a1 = __hmul2(*(const __half2*)(qp1 + kc * 16 + tg * 2), sc);
            __half2 a2 = __hmul2(*(const __half2*)(qp0 + kc * 16 + tg * 2 + 8), sc);
            __half2 a3 = __hmul2(*(const __half2*)(qp1 + kc * 16 + tg * 2 + 8), sc);
            qa[kc][0] = *(unsigned*)&a0; qa[kc][1] = *(unsigned*)&a1;
            qa[kc][2] = *(unsigned*)&a2; qa[kc][3] = *(unsigned*)&a3;
        }
    }

    float o[8][4];
#pragma unroll
    for (int nf = 0; nf < 8; nf++)
#pragma unroll
        for (int r = 0; r < 4; r++) o[nf][r] = 0.f;
    float m0 = -1e30f, m1 = -1e30f, l0 = 0.f, l1 = 0.f;

    int lrow = tid >> 2;            // 0..63
    int sec = (tid & 3) * 16;       // 0/16/32/48 halves

    int kt_max = 2 * qt + 1;        // last key tile index for this block
    for (int kt = 0; kt <= kt_max; ++kt) {
        __syncthreads();  // readers of previous tile done
        {
            const __half* kp = qkv + (size_t)(kt * 64 + lrow) * C3_ + C_ + head * 64 + sec;
            const __half* vp = kp + C_;
            *(uint4*)&Ks[lrow * KP2 + sec]     = *(const uint4*)kp;
            *(uint4*)&Ks[lrow * KP2 + sec + 8] = *(const uint4*)(kp + 8);
            *(uint4*)&Vs[lrow * KP2 + sec]     = *(const uint4*)vp;
            *(uint4*)&Vs[lrow * KP2 + sec + 8] = *(const uint4*)(vp + 8);
        }
        __syncthreads();

        // S = Q @ K^T  (warp: 16 x 64)
        float s[8][4];
#pragma unroll
        for (int nf = 0; nf < 8; nf++)
#pragma unroll
            for (int r = 0; r < 4; r++) s[nf][r] = 0.f;
#pragma unroll
        for (int kc = 0; kc < 4; kc++) {
#pragma unroll
            for (int nf = 0; nf < 8; nf++) {
                unsigned bf[2];
                bf[0] = *(const unsigned*)&Ks[(nf * 8 + g) * KP2 + kc * 16 + tg * 2];
                bf[1] = *(const unsigned*)&Ks[(nf * 8 + g) * KP2 + kc * 16 + tg * 2 + 8];
                mma_f16(s[nf], qa[kc], bf);
            }
        }

        // causal mask: only the last two key tiles can touch the diagonal
        if (kt >= 2 * qt) {
            int r0g = q0 + w * 16 + g, r1g = r0g + 8;
#pragma unroll
            for (int nf = 0; nf < 8; nf++) {
                int c0 = kt * 64 + nf * 8 + 2 * tg, c1 = c0 + 1;
                if (c0 > r0g) s[nf][0] = -1e30f;
                if (c1 > r0g) s[nf][1] = -1e30f;
                if (c0 > r1g) s[nf][2] = -1e30f;
                if (c1 > r1g) s[nf][3] = -1e30f;
            }
        }

        // online softmax
        float mx0 = -1e30f, mx1 = -1e30f;
#pragma unroll
        for (int nf = 0; nf < 8; nf++) {
            mx0 = fmaxf(mx0, fmaxf(s[nf][0], s[nf][1]));
            mx1 = fmaxf(mx1, fmaxf(s[nf][2], s[nf][3]));
        }
        mx0 = fmaxf(mx0, __shfl_xor_sync(0xffffffffu, mx0, 1));
        mx0 = fmaxf(mx0, __shfl_xor_sync(0xffffffffu, mx0, 2));
        mx1 = fmaxf(mx1, __shfl_xor_sync(0xffffffffu, mx1, 1));
        mx1 = fmaxf(mx1, __shfl_xor_sync(0xffffffffu, mx1, 2));

        float nm0 = fmaxf(m0, mx0), nm1 = fmaxf(m1, mx1);
        float f0 = __expf(m0 - nm0), f1 = __expf(m1 - nm1);
        m0 = nm0; m1 = nm1;

        float sum0 = 0.f, sum1 = 0.f;
#pragma unroll
        for (int nf = 0; nf < 8; nf++) {
            s[nf][0] = __expf(s[nf][0] - m0);
            s[nf][1] = __expf(s[nf][1] - m0);
            s[nf][2] = __expf(s[nf][2] - m1);
            s[nf][3] = __expf(s[nf][3] - m1);
            sum0 += s[nf][0] + s[nf][1];
            sum1 += s[nf][2] + s[nf][3];
        }
        sum0 += __shfl_xor_sync(0xffffffffu, sum0, 1);
        sum0 += __shfl_xor_sync(0xffffffffu, sum0, 2);
        sum1 += __shfl_xor_sync(0xffffffffu, sum1, 1);
        sum1 += __shfl_xor_sync(0xffffffffu, sum1, 2);
        l0 = l0 * f0 + sum0;
        l1 = l1 * f1 + sum1;

#pragma unroll
        for (int nf = 0; nf < 8; nf++) {
            o[nf][0] *= f0; o[nf][1] *= f0;
            o[nf][2] *= f1; o[nf][3] *= f1;
        }

        // O += P @ V : P fragments directly from the s registers
#pragma unroll
        for (int kc = 0; kc < 4; kc++) {
            unsigned pa[4];
            __half2 p0 = __floats2half2_rn(s[2 * kc][0], s[2 * kc][1]);
            __half2 p1 = __floats2half2_rn(s[2 * kc][2], s[2 * kc][3]);
            __half2 p2 = __floats2half2_rn(s[2 * kc + 1][0], s[2 * kc + 1][1]);
            __half2 p3 = __floats2half2_rn(s[2 * kc + 1][2], s[2 * kc + 1][3]);
            pa[0] = *(unsigned*)&p0; pa[1] = *(unsigned*)&p1;
            pa[2] = *(unsigned*)&p2; pa[3] = *(unsigned*)&p3;
#pragma unroll
            for (int nf = 0; nf < 8; nf++) {
                unsigned b0, b1;
                unsigned addr = (unsigned)__cvta_generic_to_shared(
                    &Vs[(kc * 16 + (lane & 15)) * KP2 + nf * 8]);
                ldsm_x2_t(b0, b1, addr);
                unsigned bv[2] = {b0, b1};
                mma_f16(o[nf], pa, bv);
            }
        }
    }

    // epilogue: normalize + write fp16
    float inv0 = 1.0f / l0, inv1 = 1.0f / l1;
    int r0 = q0 + w * 16 + g;
    __half* y0 = y + (size_t)r0 * C_ + head * 64;
    __half* y1 = y0 + (size_t)8 * C_;
#pragma unroll
    for (int nf = 0; nf < 8; nf++) {
        int c = nf * 8 + 2 * tg;
        *(__half2*)(y0 + c) = __floats2half2_rn(o[nf][0] * inv0, o[nf][1] * inv0);
        *(__half2*)(y1 + c) = __floats2half2_rn(o[nf][2] * inv1, o[nf][3] * inv1);
    }
}

// ---------------- launch ----------------
extern "C" void kernel_launch(void* const* d_in, const int* in_sizes, int n_in,
                              void* d_out, int out_size) {
    const int*   ids   = (const int*)d_in[0];
    const float* wte   = (const float*)d_in[1];
    const float* wpe   = (const float*)d_in[2];
    const float* ln1w  = (const float*)d_in[3];
    const float* ln1b  = (const float*)d_in[4];
    const float* attnw = (const float*)d_in[5];
    const float* attnb = (const float*)d_in[6];
    const float* projw = (const float*)d_in[7];
    const float* projb = (const float*)d_in[8];
    const float* ln2w  = (const float*)d_in[9];
    const float* ln2b  = (const float*)d_in[10];
    const float* fcw   = (const float*)d_in[11];
    const float* fcb   = (const float*)d_in[12];
    const float* fcpw  = (const float*)d_in[13];
    const float* fcpb  = (const float*)d_in[14];
    const float* lnfw  = (const float*)d_in[15];
    const float* lnfb  = (const float*)d_in[16];
    float* out = (float*)d_out;

    float* xp;
    __half *hp, *qkvp, *yp, *gp;
    __half *wA, *wP, *wF, *wFP, *wT;
    cudaGetSymbolAddress((void**)&xp, g_x);
    cudaGetSymbolAddress((void**)&hp, gh_h);
    cudaGetSymbolAddress((void**)&qkvp, gh_qkv);
    cudaGetSymbolAddress((void**)&yp, gh_y);
    cudaGetSymbolAddress((void**)&gp, gh_g);
    cudaGetSymbolAddress((void**)&wA, gh_attnw);
    cudaGetSymbolAddress((void**)&wP, gh_projw);
    cudaGetSymbolAddress((void**)&wF, gh_fcw);
    cudaGetSymbolAddress((void**)&wFP, gh_fcpw);
    cudaGetSymbolAddress((void**)&wT, gh_wte);

    // weight conversions (graph-capturable, deterministic)
    f2h_k<<<2048, 256>>>(attnw, wA, L_ * C3_ * C_);
    f2h_k<<<2048, 256>>>(projw, wP, L_ * C_ * C_);
    f2h_k<<<2048, 256>>>(fcw, wF, L_ * C4_ * C_);
    f2h_k<<<2048, 256>>>(fcpw, wFP, L_ * C_ * C4_);
    f2h_k<<<4096, 256>>>(wte, wT, V_ * C_);

    embed_k<<<T_, 256>>>(ids, wte, wpe, xp);

    for (int l = 0; l < L_; l++) {
        ln_k<<<T_, 256>>>(xp, ln1w + l * C_, ln1b + l * C_, hp);
        gemm_h<1, __half><<<dim3(C3_ / BN, T_ / BM), 256>>>(
            hp, wA + (size_t)l * C3_ * C_, attnb + l * C3_, qkvp, T_, C3_, C_);
        attn_k<<<dim3(T_ / 128, H_), 256>>>(qkvp, yp);
        gemm_h<3, float><<<dim3(C_ / BN, T_ / BM), 256>>>(
            yp, wP + (size_t)l * C_ * C_, projb + l * C_, xp, T_, C_, C_);
        ln_k<<<T_, 256>>>(xp, ln2w + l * C_, ln2b + l * C_, hp);
        gemm_h<5, __half><<<dim3(C4_ / BN, T_ / BM), 256>>>(
            hp, wF + (size_t)l * C4_ * C_, fcb + l * C4_, gp, T_, C4_, C_);
        gemm_h<3, float><<<dim3(C_ / BN, T_ / BM), 256>>>(
            gp, wFP + (size_t)l * C_ * C4_, fcpb + l * C_, xp, T_, C_, C4_);
    }

    ln_k<<<T_, 256>>>(xp, lnfw, lnfb, hp);
    gemm_h<0, float><<<dim3(V_ / BN, T_ / BM), 256>>>(
        hp, wT, nullptr, out, T_, V_, C_);
}